// round 13
// baseline (speedup 1.0000x reference)
#include <cuda_runtime.h>
#include <mma.h>
#include <cstdint>
#include <cstddef>

using namespace nvcuda;

#define N_NODES 10000
#define N_EDGES 320000
#define D 128
#define H 512

#define BM 128        // edges/nodes per block
#define THREADS 512   // 16 warps, 4x4 warp grid, 32x32 warp tiles
#define A_LD 36       // padded ld for gathered-input tiles [128][32]
#define T_LD 132      // padded ld for 128-wide tiles

// scratch: per-node aggregation buffer (allocation-free rule -> __device__ global)
__device__ float g_agg[N_NODES * D];
__device__ int g_is64;   // 1 if edge_index is int64, 0 if int32

// ---------------------------------------------------------------------------
// prep: zero aggregation buffer + sniff edge_index dtype.
// int64 values < 2^31 => every odd 32-bit word is 0 (little-endian). int32 =>
// odd words are random node ids (P(all 16 zero) ~ 1e-64).
// ---------------------------------------------------------------------------
__global__ void in_prep_kernel(const int* __restrict__ eidx_words) {
    int i = blockIdx.x * blockDim.x + threadIdx.x;
    if (i < N_NODES * D) g_agg[i] = 0.0f;
    if (blockIdx.x == 0 && threadIdx.x == 0) {
        int any = 0;
#pragma unroll
        for (int t = 0; t < 16; t++) any |= eidx_words[2 * t + 1];
        g_is64 = (any == 0) ? 1 : 0;
    }
}

// ---------------------------------------------------------------------------
// Edge MLP: out_e = relu([x_s | x_r | e_a] @ W1 + b1) @ W2 + b2
// Fused: gather + GEMM1(384->512 in hidden chunks of 128) + relu +
// GEMM2(512->128) + scatter-add into g_agg.
// tf32 WMMA, fp32 accumulate, register-staged double buffering on K-chunks.
// ---------------------------------------------------------------------------
__global__ __launch_bounds__(THREADS, 1)
void edge_mlp_kernel(const float* __restrict__ x,
                     const void*  __restrict__ eidx,
                     const float* __restrict__ edge_attr,
                     const float* __restrict__ W1,
                     const float* __restrict__ b1,
                     const float* __restrict__ W2,
                     const float* __restrict__ b2,
                     float* __restrict__ out_edge) {
    extern __shared__ float sm[];
    float* A_sh   = sm;                       // [128][A_LD] gathered input chunk
    float* W1_sh  = A_sh  + BM * A_LD;        // [32][T_LD]
    float* hid_sh = W1_sh + 32 * T_LD;        // [128][T_LD] hidden chunk / out tile
    float* W2_sh  = hid_sh + BM * T_LD;       // [32][T_LD]
    int*   s_sh   = (int*)(W2_sh + 32 * T_LD);
    int*   r_sh   = s_sh + BM;

    const int tid = threadIdx.x;
    const int wid = tid >> 5;
    const int wr  = wid >> 2;   // warp row 0..3 (32 edges each)
    const int wc  = wid & 3;    // warp col 0..3 (32 outputs each)
    const int e0  = blockIdx.x * BM;

    if (tid < BM) {
        long long s, r;
        if (g_is64) {
            const long long* p = (const long long*)eidx;
            s = p[e0 + tid]; r = p[N_EDGES + e0 + tid];
        } else {
            const int* p = (const int*)eidx;
            s = p[e0 + tid]; r = p[N_EDGES + e0 + tid];
        }
        s_sh[tid] = (int)s; r_sh[tid] = (int)r;
    }
    __syncthreads();

    // per-thread tile coordinates for staged loads (2 float4 each for A and W)
    const int am0 = (tid)           >> 3, ac0 = ((tid)           & 7) * 4;
    const int am1 = (tid + THREADS) >> 3, ac1 = ((tid + THREADS) & 7) * 4;
    const int wk0 = (tid)           >> 5, wc0 = ((tid)           & 31) * 4;
    const int wk1 = (tid + THREADS) >> 5, wc1 = ((tid + THREADS) & 31) * 4;

    // gather one float4 of the [128][32] A tile for K-chunk kc (K = 384 total)
    auto ldA = [&](int kc, int m, int c) -> float4 {
        int kk = kc * 32 + c;
        if (kk < D)          return *(const float4*)(x + (size_t)s_sh[m] * D + kk);
        else if (kk < 2 * D) return *(const float4*)(x + (size_t)r_sh[m] * D + (kk - D));
        else                 return *(const float4*)(edge_attr + (size_t)(e0 + m) * D + (kk - 2 * D));
    };

    wmma::fragment<wmma::accumulator, 16, 16, 8, float> oacc[2][2];
#pragma unroll
    for (int i = 0; i < 2; i++)
#pragma unroll
        for (int j = 0; j < 2; j++) wmma::fill_fragment(oacc[i][j], 0.0f);

    for (int hc = 0; hc < 4; hc++) {       // hidden chunks of 128
        wmma::fragment<wmma::accumulator, 16, 16, 8, float> hacc[2][2];
#pragma unroll
        for (int i = 0; i < 2; i++)
#pragma unroll
            for (int j = 0; j < 2; j++) wmma::fill_fragment(hacc[i][j], 0.0f);

        // ---- GEMM1: [128,384] @ [384,128] in 12 K-chunks, pipelined ----
        float4 pA0 = ldA(0, am0, ac0);
        float4 pA1 = ldA(0, am1, ac1);
        float4 pW0 = *(const float4*)(W1 + (size_t)(wk0) * H + hc * 128 + wc0);
        float4 pW1 = *(const float4*)(W1 + (size_t)(wk1) * H + hc * 128 + wc1);
        *(float4*)(A_sh + am0 * A_LD + ac0) = pA0;
        *(float4*)(A_sh + am1 * A_LD + ac1) = pA1;
        *(float4*)(W1_sh + wk0 * T_LD + wc0) = pW0;
        *(float4*)(W1_sh + wk1 * T_LD + wc1) = pW1;
        __syncthreads();

        for (int kc = 0; kc < 12; kc++) {
            if (kc < 11) {   // prefetch next chunk into registers (overlaps mma)
                pA0 = ldA(kc + 1, am0, ac0);
                pA1 = ldA(kc + 1, am1, ac1);
                pW0 = *(const float4*)(W1 + (size_t)((kc + 1) * 32 + wk0) * H + hc * 128 + wc0);
                pW1 = *(const float4*)(W1 + (size_t)((kc + 1) * 32 + wk1) * H + hc * 128 + wc1);
            }
#pragma unroll
            for (int ks = 0; ks < 4; ks++) {
                wmma::fragment<wmma::matrix_a, 16, 16, 8, wmma::precision::tf32, wmma::row_major> af[2];
                wmma::fragment<wmma::matrix_b, 16, 16, 8, wmma::precision::tf32, wmma::row_major> bf[2];
#pragma unroll
                for (int i = 0; i < 2; i++) {
                    wmma::load_matrix_sync(af[i], A_sh + (size_t)(wr * 32 + i * 16) * A_LD + ks * 8, A_LD);
#pragma unroll
                    for (int t = 0; t < af[i].num_elements; t++)
                        af[i].x[t] = wmma::__float_to_tf32(af[i].x[t]);
                }
#pragma unroll
                for (int j = 0; j < 2; j++) {
                    wmma::load_matrix_sync(bf[j], W1_sh + (size_t)(ks * 8) * T_LD + wc * 32 + j * 16, T_LD);
#pragma unroll
                    for (int t = 0; t < bf[j].num_elements; t++)
                        bf[j].x[t] = wmma::__float_to_tf32(bf[j].x[t]);
                }
#pragma unroll
                for (int i = 0; i < 2; i++)
#pragma unroll
                    for (int j = 0; j < 2; j++)
                        wmma::mma_sync(hacc[i][j], af[i], bf[j], hacc[i][j]);
            }
            __syncthreads();           // all warps done reading chunk kc
            if (kc < 11) {
                *(float4*)(A_sh + am0 * A_LD + ac0) = pA0;
                *(float4*)(A_sh + am1 * A_LD + ac1) = pA1;
                *(float4*)(W1_sh + wk0 * T_LD + wc0) = pW0;
                *(float4*)(W1_sh + wk1 * T_LD + wc1) = pW1;
                __syncthreads();       // chunk kc+1 visible
            }
        }

        // hidden chunk -> smem, bias+relu
#pragma unroll
        for (int i = 0; i < 2; i++)
#pragma unroll
            for (int j = 0; j < 2; j++)
                wmma::store_matrix_sync(hid_sh + (size_t)(wr * 32 + i * 16) * T_LD + wc * 32 + j * 16,
                                        hacc[i][j], T_LD, wmma::mem_row_major);
        __syncthreads();
        for (int i = tid; i < BM * 128; i += THREADS) {
            int m = i >> 7, c = i & 127;
            float v = hid_sh[m * T_LD + c] + b1[hc * 128 + c];
            hid_sh[m * T_LD + c] = fmaxf(v, 0.0f);
        }

        // ---- GEMM2 partial: oacc += relu_chunk @ W2[hc*128:(hc+1)*128, :] ----
        pW0 = *(const float4*)(W2 + (size_t)(hc * 128 + wk0) * D + wc0);
        pW1 = *(const float4*)(W2 + (size_t)(hc * 128 + wk1) * D + wc1);
        __syncthreads();               // relu writes visible; W2_sh free
        *(float4*)(W2_sh + wk0 * T_LD + wc0) = pW0;
        *(float4*)(W2_sh + wk1 * T_LD + wc1) = pW1;
        __syncthreads();

        for (int k2 = 0; k2 < 4; k2++) {
            if (k2 < 3) {
                pW0 = *(const float4*)(W2 + (size_t)(hc * 128 + (k2 + 1) * 32 + wk0) * D + wc0);
                pW1 = *(const float4*)(W2 + (size_t)(hc * 128 + (k2 + 1) * 32 + wk1) * D + wc1);
            }
#pragma unroll
            for (int ks = 0; ks < 4; ks++) {
                wmma::fragment<wmma::matrix_a, 16, 16, 8, wmma::precision::tf32, wmma::row_major> af[2];
                wmma::fragment<wmma::matrix_b, 16, 16, 8, wmma::precision::tf32, wmma::row_major> bf[2];
#pragma unroll
                for (int i = 0; i < 2; i++) {
                    wmma::load_matrix_sync(af[i], hid_sh + (size_t)(wr * 32 + i * 16) * T_LD + k2 * 32 + ks * 8, T_LD);
#pragma unroll
                    for (int t = 0; t < af[i].num_elements; t++)
                        af[i].x[t] = wmma::__float_to_tf32(af[i].x[t]);
                }
#pragma unroll
                for (int j = 0; j < 2; j++) {
                    wmma::load_matrix_sync(bf[j], W2_sh + (size_t)(ks * 8) * T_LD + wc * 32 + j * 16, T_LD);
#pragma unroll
                    for (int t = 0; t < bf[j].num_elements; t++)
                        bf[j].x[t] = wmma::__float_to_tf32(bf[j].x[t]);
                }
#pragma unroll
                for (int i = 0; i < 2; i++)
#pragma unroll
                    for (int j = 0; j < 2; j++)
                        wmma::mma_sync(oacc[i][j], af[i], bf[j], oacc[i][j]);
            }
            __syncthreads();
            if (k2 < 3) {
                *(float4*)(W2_sh + wk0 * T_LD + wc0) = pW0;
                *(float4*)(W2_sh + wk1 * T_LD + wc1) = pW1;
                __syncthreads();
            }
        }
    }

    // epilogue: oacc -> smem, bias, write updated_edge_attr, scatter-add
#pragma unroll
    for (int i = 0; i < 2; i++)
#pragma unroll
        for (int j = 0; j < 2; j++)
            wmma::store_matrix_sync(hid_sh + (size_t)(wr * 32 + i * 16) * T_LD + wc * 32 + j * 16,
                                    oacc[i][j], T_LD, wmma::mem_row_major);
    __syncthreads();

    for (int i = tid; i < BM * D; i += THREADS) {
        int m = i >> 7, c = i & 127;
        float v = hid_sh[m * T_LD + c] + b2[c];
        out_edge[(size_t)(e0 + m) * D + c] = v;
        atomicAdd(&g_agg[(size_t)r_sh[m] * D + c], v);
    }
}

// ---------------------------------------------------------------------------
// Node MLP: out_n = relu([x | agg] @ Wn1 + bn1) @ Wn2 + bn2   (K = 256)
// Same pipelined structure.
// ---------------------------------------------------------------------------
__global__ __launch_bounds__(THREADS, 1)
void node_mlp_kernel(const float* __restrict__ x,
                     const float* __restrict__ W1,
                     const float* __restrict__ b1,
                     const float* __restrict__ W2,
                     const float* __restrict__ b2,
                     float* __restrict__ out_nodes) {
    extern __shared__ float sm[];
    float* A_sh   = sm;                 // [128][A_LD]
    float* W1_sh  = A_sh  + BM * A_LD;  // [32][T_LD]
    float* hid_sh = W1_sh + 32 * T_LD;  // [128][T_LD]
    float* W2_sh  = hid_sh + BM * T_LD; // [32][T_LD]

    const int tid = threadIdx.x;
    const int wid = tid >> 5;
    const int wr  = wid >> 2;
    const int wc  = wid & 3;
    const int n0  = blockIdx.x * BM;

    const int am0 = (tid)           >> 3, ac0 = ((tid)           & 7) * 4;
    const int am1 = (tid + THREADS) >> 3, ac1 = ((tid + THREADS) & 7) * 4;
    const int wk0 = (tid)           >> 5, wc0 = ((tid)           & 31) * 4;
    const int wk1 = (tid + THREADS) >> 5, wc1 = ((tid + THREADS) & 31) * 4;

    auto ldA = [&](int kc, int m, int c) -> float4 {
        int n = n0 + m;
        if (n >= N_NODES) return make_float4(0.f, 0.f, 0.f, 0.f);
        int kk = kc * 32 + c;
        if (kk < D) return *(const float4*)(x + (size_t)n * D + kk);
        else        return *(const float4*)(g_agg + (size_t)n * D + (kk - D));
    };

    wmma::fragment<wmma::accumulator, 16, 16, 8, float> oacc[2][2];
#pragma unroll
    for (int i = 0; i < 2; i++)
#pragma unroll
        for (int j = 0; j < 2; j++) wmma::fill_fragment(oacc[i][j], 0.0f);

    for (int hc = 0; hc < 4; hc++) {
        wmma::fragment<wmma::accumulator, 16, 16, 8, float> hacc[2][2];
#pragma unroll
        for (int i = 0; i < 2; i++)
#pragma unroll
            for (int j = 0; j < 2; j++) wmma::fill_fragment(hacc[i][j], 0.0f);

        float4 pA0 = ldA(0, am0, ac0);
        float4 pA1 = ldA(0, am1, ac1);
        float4 pW0 = *(const float4*)(W1 + (size_t)(wk0) * H + hc * 128 + wc0);
        float4 pW1 = *(const float4*)(W1 + (size_t)(wk1) * H + hc * 128 + wc1);
        *(float4*)(A_sh + am0 * A_LD + ac0) = pA0;
        *(float4*)(A_sh + am1 * A_LD + ac1) = pA1;
        *(float4*)(W1_sh + wk0 * T_LD + wc0) = pW0;
        *(float4*)(W1_sh + wk1 * T_LD + wc1) = pW1;
        __syncthreads();

        for (int kc = 0; kc < 8; kc++) {   // K = 256
            if (kc < 7) {
                pA0 = ldA(kc + 1, am0, ac0);
                pA1 = ldA(kc + 1, am1, ac1);
                pW0 = *(const float4*)(W1 + (size_t)((kc + 1) * 32 + wk0) * H + hc * 128 + wc0);
                pW1 = *(const float4*)(W1 + (size_t)((kc + 1) * 32 + wk1) * H + hc * 128 + wc1);
            }
#pragma unroll
            for (int ks = 0; ks < 4; ks++) {
                wmma::fragment<wmma::matrix_a, 16, 16, 8, wmma::precision::tf32, wmma::row_major> af[2];
                wmma::fragment<wmma::matrix_b, 16, 16, 8, wmma::precision::tf32, wmma::row_major> bf[2];
#pragma unroll
                for (int i = 0; i < 2; i++) {
                    wmma::load_matrix_sync(af[i], A_sh + (size_t)(wr * 32 + i * 16) * A_LD + ks * 8, A_LD);
#pragma unroll
                    for (int t = 0; t < af[i].num_elements; t++)
                        af[i].x[t] = wmma::__float_to_tf32(af[i].x[t]);
                }
#pragma unroll
                for (int j = 0; j < 2; j++) {
                    wmma::load_matrix_sync(bf[j], W1_sh + (size_t)(ks * 8) * T_LD + wc * 32 + j * 16, T_LD);
#pragma unroll
                    for (int t = 0; t < bf[j].num_elements; t++)
                        bf[j].x[t] = wmma::__float_to_tf32(bf[j].x[t]);
                }
#pragma unroll
                for (int i = 0; i < 2; i++)
#pragma unroll
                    for (int j = 0; j < 2; j++)
                        wmma::mma_sync(hacc[i][j], af[i], bf[j], hacc[i][j]);
            }
            __syncthreads();
            if (kc < 7) {
                *(float4*)(A_sh + am0 * A_LD + ac0) = pA0;
                *(float4*)(A_sh + am1 * A_LD + ac1) = pA1;
                *(float4*)(W1_sh + wk0 * T_LD + wc0) = pW0;
                *(float4*)(W1_sh + wk1 * T_LD + wc1) = pW1;
                __syncthreads();
            }
        }

#pragma unroll
        for (int i = 0; i < 2; i++)
#pragma unroll
            for (int j = 0; j < 2; j++)
                wmma::store_matrix_sync(hid_sh + (size_t)(wr * 32 + i * 16) * T_LD + wc * 32 + j * 16,
                                        hacc[i][j], T_LD, wmma::mem_row_major);
        __syncthreads();
        for (int i = tid; i < BM * 128; i += THREADS) {
            int m = i >> 7, c = i & 127;
            float v = hid_sh[m * T_LD + c] + b1[hc * 128 + c];
            hid_sh[m * T_LD + c] = fmaxf(v, 0.0f);
        }

        float4 qW0 = *(const float4*)(W2 + (size_t)(hc * 128 + wk0) * D + wc0);
        float4 qW1 = *(const float4*)(W2 + (size_t)(hc * 128 + wk1) * D + wc1);
        __syncthreads();
        *(float4*)(W2_sh + wk0 * T_LD + wc0) = qW0;
        *(float4*)(W2_sh + wk1 * T_LD + wc1) = qW1;
        __syncthreads();

        for (int k2 = 0; k2 < 4; k2++) {
            if (k2 < 3) {
                qW0 = *(const float4*)(W2 + (size_t)(hc * 128 + (k2 + 1) * 32 + wk0) * D + wc0);
                qW1 = *(const float4*)(W2 + (size_t)(hc * 128 + (k2 + 1) * 32 + wk1) * D + wc1);
            }
#pragma unroll
            for (int ks = 0; ks < 4; ks++) {
                wmma::fragment<wmma::matrix_a, 16, 16, 8, wmma::precision::tf32, wmma::row_major> af[2];
                wmma::fragment<wmma::matrix_b, 16, 16, 8, wmma::precision::tf32, wmma::row_major> bf[2];
#pragma unroll
                for (int i = 0; i < 2; i++) {
                    wmma::load_matrix_sync(af[i], hid_sh + (size_t)(wr * 32 + i * 16) * T_LD + k2 * 32 + ks * 8, T_LD);
#pragma unroll
                    for (int t = 0; t < af[i].num_elements; t++)
                        af[i].x[t] = wmma::__float_to_tf32(af[i].x[t]);
                }
#pragma unroll
                for (int j = 0; j < 2; j++) {
                    wmma::load_matrix_sync(bf[j], W2_sh + (size_t)(ks * 8) * T_LD + wc * 32 + j * 16, T_LD);
#pragma unroll
                    for (int t = 0; t < bf[j].num_elements; t++)
                        bf[j].x[t] = wmma::__float_to_tf32(bf[j].x[t]);
                }
#pragma unroll
                for (int i = 0; i < 2; i++)
#pragma unroll
                    for (int j = 0; j < 2; j++)
                        wmma::mma_sync(oacc[i][j], af[i], bf[j], oacc[i][j]);
            }
            __syncthreads();
            if (k2 < 3) {
                *(float4*)(W2_sh + wk0 * T_LD + wc0) = qW0;
                *(float4*)(W2_sh + wk1 * T_LD + wc1) = qW1;
                __syncthreads();
            }
        }
    }

#pragma unroll
    for (int i = 0; i < 2; i++)
#pragma unroll
        for (int j = 0; j < 2; j++)
            wmma::store_matrix_sync(hid_sh + (size_t)(wr * 32 + i * 16) * T_LD + wc * 32 + j * 16,
                                    oacc[i][j], T_LD, wmma::mem_row_major);
    __syncthreads();

    for (int i = tid; i < BM * D; i += THREADS) {
        int m = i >> 7, c = i & 127;
        int n = n0 + m;
        if (n < N_NODES) {
            float v = hid_sh[m * T_LD + c] + b2[c];
            out_nodes[(size_t)n * D + c] = v;
        }
    }
}

// ---------------------------------------------------------------------------
extern "C" void kernel_launch(void* const* d_in, const int* in_sizes, int n_in,
                              void* d_out, int out_size) {
    const float* x    = (const float*)d_in[0];
    const void*  eidx = d_in[1];
    const float* ea   = (const float*)d_in[2];
    const float* We1  = (const float*)d_in[3];
    const float* be1  = (const float*)d_in[4];
    const float* We2  = (const float*)d_in[5];
    const float* be2  = (const float*)d_in[6];
    const float* Wn1  = (const float*)d_in[7];
    const float* bn1  = (const float*)d_in[8];
    const float* Wn2  = (const float*)d_in[9];
    const float* bn2  = (const float*)d_in[10];

    float* out_nodes = (float*)d_out;                         // [N_NODES, D]
    float* out_edges = out_nodes + (size_t)N_NODES * D;       // [N_EDGES, D]

    const size_t smem_main =
        (size_t)(BM * A_LD + 32 * T_LD + BM * T_LD + 32 * T_LD) * sizeof(float)
        + 2 * BM * sizeof(int);

    cudaFuncSetAttribute(edge_mlp_kernel, cudaFuncAttributeMaxDynamicSharedMemorySize, (int)smem_main);
    cudaFuncSetAttribute(node_mlp_kernel, cudaFuncAttributeMaxDynamicSharedMemorySize, (int)smem_main);

    in_prep_kernel<<<(N_NODES * D + 511) / 512, 512>>>((const int*)eidx);
    edge_mlp_kernel<<<N_EDGES / BM, THREADS, smem_main>>>(
        x, eidx, ea, We1, be1, We2, be2, out_edges);
    node_mlp_kernel<<<(N_NODES + BM - 1) / BM, THREADS, smem_main>>>(
        x, Wn1, bn1, Wn2, bn2, out_nodes);
}